// round 15
// baseline (speedup 1.0000x reference)
#include <cuda_runtime.h>
#include <math.h>

#define NB   8
#define NH   16
#define LQ   128
#define LC   4096
#define DD   1024
#define HL   (NH * LQ)   // 2048
#define TOPK 5
#define EPS  1e-8f

// Scratch (__device__ globals; zero-initialized at load; tail resets what it
// reads, so graph replays are self-consistent with no zero kernel).
__device__ float g_avg[NB * LC];
__device__ float g_qvec[NB * DD];
__device__ float g_loss_sum;
__device__ int   g_done;

// ---------------------------------------------------------------------------
// helpers
// ---------------------------------------------------------------------------
__device__ __forceinline__ float warp_sum(float v) {
    #pragma unroll
    for (int off = 16; off > 0; off >>= 1)
        v += __shfl_down_sync(0xffffffffu, v, off);
    return v;
}
// butterfly max: every lane ends with the warp max
__device__ __forceinline__ unsigned long long warp_max64_all(unsigned long long k) {
    #pragma unroll
    for (int off = 16; off > 0; off >>= 1) {
        unsigned long long o = __shfl_xor_sync(0xffffffffu, k, off);
        if (o > k) k = o;
    }
    return k;
}
// orderable mapping: preserves float total order as unsigned compare
__device__ __forceinline__ unsigned ord(float f) {
    unsigned fb = __float_as_uint(f);
    unsigned m  = (unsigned)((int)fb >> 31);
    return fb ^ (m | 0x80000000u);
}

// ---------------------------------------------------------------------------
// 1. Stream (R14-proven: scheme A geometry + __ldcs evict-first, ~6.4 TB/s,
//    8/8 correct top-k selections): 1024 attn blocks (64-row sequential
//    chunks, 32-way atomic merge) + 64 qvec blocks.
// ---------------------------------------------------------------------------
__global__ void __launch_bounds__(256)
fused_reduce(const float4* __restrict__ w, const float4* __restrict__ q) {
    const int id = blockIdx.x;

    if (id < 1024) {                       // ---- attn part (256 MB read) ----
        const int b      = id >> 7;
        const int rem    = id & 127;
        const int seg    = rem >> 2;       // 0..31
        const int cchunk = rem & 3;        // 0..3
        const int lc4    = cchunk * 256 + threadIdx.x;
        const int ROWS   = HL / 32;        // 64

        float4 acc = make_float4(0.f, 0.f, 0.f, 0.f);
        const float4* p = w + ((size_t)b * HL + (size_t)seg * ROWS) * (LC / 4) + lc4;

        #pragma unroll 16
        for (int r = 0; r < ROWS; r++) {
            float4 v = __ldcs(p + (size_t)r * (LC / 4));   // evict-first
            acc.x += v.x; acc.y += v.y; acc.z += v.z; acc.w += v.w;
        }
        float* dst = &g_avg[b * LC + lc4 * 4];
        atomicAdd(dst + 0, acc.x);
        atomicAdd(dst + 1, acc.y);
        atomicAdd(dst + 2, acc.z);
        atomicAdd(dst + 3, acc.w);
    } else {                               // ---- question part (4 MB) ----
        const int id2 = id - 1024;
        const int b   = id2 >> 3;
        const int seg = id2 & 7;           // 16 lq rows each
        const int tid = threadIdx.x;

        float4 acc = make_float4(0.f, 0.f, 0.f, 0.f);
        const float4* p = q + ((size_t)b * LQ + (size_t)seg * 16) * (DD / 4) + tid;

        #pragma unroll
        for (int r = 0; r < 16; r++) {
            float4 v = __ldcs(p + (size_t)r * (DD / 4));   // evict-first
            acc.x += v.x; acc.y += v.y; acc.z += v.z; acc.w += v.w;
        }
        float* dst = &g_qvec[b * DD + tid * 4];
        atomicAdd(dst + 0, acc.x);
        atomicAdd(dst + 1, acc.y);
        atomicAdd(dst + 2, acc.z);
        atomicAdd(dst + 3, acc.w);
    }
}

// ---------------------------------------------------------------------------
// 2. Tail (R11/R14 body): per-batch top-5 (min-index tie-break = jax top_k)
//    + cosine vs mean question vector; global mean by ticket; resets scratch.
//    Plain launch — R8 vs R11/R13/R14 tail durations suggest PDL costs ~1 us
//    here and hides nothing. grid: NB x 256 threads.
// ---------------------------------------------------------------------------
__global__ void __launch_bounds__(256, 1)
tail_kernel(const float* __restrict__ ctx, float* __restrict__ out) {
    __shared__ float              s_wv[8];
    __shared__ unsigned long long s_cand[8 * TOPK];   // 40 candidates
    __shared__ int                s_top[TOPK];
    __shared__ float              s_qn;
    __shared__ float              s_red[2 * TOPK][8];

    const int b    = blockIdx.x;
    const int tid  = threadIdx.x;
    const int lane = tid & 31;
    const int wid  = tid >> 5;
    const float4 zero4 = make_float4(0.f, 0.f, 0.f, 0.f);

    // --- issue all g_avg loads first (4 independent LDG.128, L2-hot) ------
    float4 av[4];
    #pragma unroll
    for (int j = 0; j < 4; j++)
        av[j] = reinterpret_cast<const float4*>(g_avg)[b * (LC / 4) + tid + j * 256];

    // --- mean question vector + norm partial (overlaps the loads above) ---
    float4 q4 = reinterpret_cast<const float4*>(g_qvec)[b * (DD / 4) + tid];
    const float inv = 1.0f / (float)LQ;    // *2^-7: exact
    q4.x *= inv; q4.y *= inv; q4.z *= inv; q4.w *= inv;
    {
        float p = warp_sum(q4.x * q4.x + q4.y * q4.y + q4.z * q4.z + q4.w * q4.w);
        if (lane == 0) s_wv[wid] = p;
    }
    reinterpret_cast<float4*>(g_qvec)[b * (DD / 4) + tid] = zero4;

    // --- single-pass local top-5: sorted-descending key list in registers --
    unsigned long long key[TOPK] = {0ull, 0ull, 0ull, 0ull, 0ull};
    #pragma unroll
    for (int j = 0; j < 4; j++) {
        const float vv[4] = {av[j].x, av[j].y, av[j].z, av[j].w};
        #pragma unroll
        for (int c = 0; c < 4; c++) {
            int idx = (tid + j * 256) * 4 + c;
            unsigned long long k =
                ((unsigned long long)ord(vv[c]) << 32) | (unsigned)(LC - 1 - idx);
            #pragma unroll
            for (int m = 0; m < TOPK; m++) {
                unsigned long long mx = (key[m] > k) ? key[m] : k;
                k      = (key[m] > k) ? k : key[m];
                key[m] = mx;
            }
        }
        // reset scratch for next replay
        reinterpret_cast<float4*>(g_avg)[b * (LC / 4) + tid + j * 256] = zero4;
    }

    // --- per-warp top-5 via butterfly max (no block syncs) ------------------
    #pragma unroll
    for (int r = 0; r < TOPK; r++) {
        unsigned long long m = warp_max64_all(key[0]);
        if (lane == 0) s_cand[wid * TOPK + r] = m;
        if (key[0] == m) {                 // unique keys: exactly one popper
            key[0] = key[1]; key[1] = key[2];
            key[2] = key[3]; key[3] = key[4]; key[4] = 0ull;
        }
    }
    __syncthreads();                       // barrier 1: candidates + s_wv

    // --- warp0: qnorm + merge 40 candidates -> block top-5 ------------------
    if (wid == 0) {
        float v = (lane < 8) ? s_wv[lane] : 0.0f;
        v = warp_sum(v);
        if (lane == 0) s_qn = fmaxf(sqrtf(v), EPS);

        unsigned long long a  = s_cand[lane];
        unsigned long long c1 = (lane < 8) ? s_cand[32 + lane] : 0ull;
        unsigned long long hi = (a > c1) ? a : c1;
        unsigned long long lo = (a > c1) ? c1 : a;
        #pragma unroll
        for (int r = 0; r < TOPK; r++) {
            unsigned long long m = warp_max64_all(hi);
            if (lane == 0)
                s_top[r] = LC - 1 - (int)(unsigned)(m & 0xffffffffu);
            if (hi == m) { hi = lo; lo = 0ull; }
        }
    }
    __syncthreads();                       // barrier 2: s_top ready

    // --- batched gather of all 5 context rows (one DRAM round-trip) ---------
    float4 cv[TOPK];
    #pragma unroll
    for (int k = 0; k < TOPK; k++)
        cv[k] = reinterpret_cast<const float4*>(ctx)
                    [((size_t)b * LC + (size_t)s_top[k]) * (DD / 4) + tid];

    // --- all 10 partial reductions, single barrier ---------------------------
    #pragma unroll
    for (int k = 0; k < TOPK; k++) {
        float d = warp_sum(cv[k].x * q4.x + cv[k].y * q4.y +
                           cv[k].z * q4.z + cv[k].w * q4.w);
        float n = warp_sum(cv[k].x * cv[k].x + cv[k].y * cv[k].y +
                           cv[k].z * cv[k].z + cv[k].w * cv[k].w);
        if (lane == 0) { s_red[k][wid] = d; s_red[TOPK + k][wid] = n; }
    }
    __syncthreads();                       // barrier 3: partials ready

    if (wid == 0) {
        float loss = 0.0f;
        #pragma unroll
        for (int k = 0; k < TOPK; k++) {
            float dd = warp_sum((lane < 8) ? s_red[k][lane] : 0.0f);
            float nn = warp_sum((lane < 8) ? s_red[TOPK + k][lane] : 0.0f);
            if (lane == 0)
                loss += 1.0f - dd / (s_qn * fmaxf(sqrtf(nn), EPS));
        }
        if (lane == 0) {
            atomicAdd(&g_loss_sum, loss);
            __threadfence();
            int t = atomicAdd(&g_done, 1);
            if (t == NB - 1) {
                __threadfence();
                float total = atomicAdd(&g_loss_sum, 0.0f);  // coherent read
                out[0] = total / (float)(NB * TOPK);
                g_loss_sum = 0.0f;             // reset for next replay
                g_done     = 0;
            }
        }
    }
}

// ---------------------------------------------------------------------------
extern "C" void kernel_launch(void* const* d_in, const int* in_sizes, int n_in,
                              void* d_out, int out_size) {
    const float* q   = (const float*)d_in[0];  // question_emb  [8,128,1024]
    const float* ctx = (const float*)d_in[1];  // context_emb   [8,4096,1024]
    const float* w   = (const float*)d_in[2];  // cross_attn    [8,16,128,4096]

    fused_reduce<<<1024 + 64, 256>>>((const float4*)w, (const float4*)q);
    tail_kernel<<<NB, 256>>>(ctx, (float*)d_out);
}

// round 16
// speedup vs baseline: 1.0412x; 1.0412x over previous
#include <cuda_runtime.h>
#include <math.h>

#define NB   8
#define NH   16
#define LQ   128
#define LC   4096
#define DD   1024
#define HL   (NH * LQ)   // 2048
#define TOPK 5
#define EPS  1e-8f

// Scratch (__device__ globals; zero-initialized at load; tail resets what it
// reads, so graph replays are self-consistent with no zero kernel).
__device__ float g_avg[NB * LC];
__device__ float g_qvec[NB * DD];
__device__ float g_loss_sum;
__device__ int   g_done;

// ---------------------------------------------------------------------------
// helpers
// ---------------------------------------------------------------------------
__device__ __forceinline__ float warp_sum(float v) {
    #pragma unroll
    for (int off = 16; off > 0; off >>= 1)
        v += __shfl_down_sync(0xffffffffu, v, off);
    return v;
}
// butterfly max: every lane ends with the warp max
__device__ __forceinline__ unsigned long long warp_max64_all(unsigned long long k) {
    #pragma unroll
    for (int off = 16; off > 0; off >>= 1) {
        unsigned long long o = __shfl_xor_sync(0xffffffffu, k, off);
        if (o > k) k = o;
    }
    return k;
}
// orderable mapping: preserves float total order as unsigned compare
__device__ __forceinline__ unsigned ord(float f) {
    unsigned fb = __float_as_uint(f);
    unsigned m  = (unsigned)((int)fb >> 31);
    return fb ^ (m | 0x80000000u);
}

// ---------------------------------------------------------------------------
// 1. Stream (R14-proven, byte-identical: scheme A + __ldcs, ~6.4 TB/s):
//    1024 attn blocks (64-row sequential chunks, 32-way atomic merge)
//    + 64 qvec blocks. PDL trigger after the atomics.
// ---------------------------------------------------------------------------
__global__ void __launch_bounds__(256)
fused_reduce(const float4* __restrict__ w, const float4* __restrict__ q) {
    const int id = blockIdx.x;

    if (id < 1024) {                       // ---- attn part (256 MB read) ----
        const int b      = id >> 7;
        const int rem    = id & 127;
        const int seg    = rem >> 2;       // 0..31
        const int cchunk = rem & 3;        // 0..3
        const int lc4    = cchunk * 256 + threadIdx.x;
        const int ROWS   = HL / 32;        // 64

        float4 acc = make_float4(0.f, 0.f, 0.f, 0.f);
        const float4* p = w + ((size_t)b * HL + (size_t)seg * ROWS) * (LC / 4) + lc4;

        #pragma unroll 16
        for (int r = 0; r < ROWS; r++) {
            float4 v = __ldcs(p + (size_t)r * (LC / 4));   // evict-first
            acc.x += v.x; acc.y += v.y; acc.z += v.z; acc.w += v.w;
        }
        float* dst = &g_avg[b * LC + lc4 * 4];
        atomicAdd(dst + 0, acc.x);
        atomicAdd(dst + 1, acc.y);
        atomicAdd(dst + 2, acc.z);
        atomicAdd(dst + 3, acc.w);
    } else {                               // ---- question part (4 MB) ----
        const int id2 = id - 1024;
        const int b   = id2 >> 3;
        const int seg = id2 & 7;           // 16 lq rows each
        const int tid = threadIdx.x;

        float4 acc = make_float4(0.f, 0.f, 0.f, 0.f);
        const float4* p = q + ((size_t)b * LQ + (size_t)seg * 16) * (DD / 4) + tid;

        #pragma unroll
        for (int r = 0; r < 16; r++) {
            float4 v = __ldcs(p + (size_t)r * (DD / 4));   // evict-first
            acc.x += v.x; acc.y += v.y; acc.z += v.z; acc.w += v.w;
        }
        float* dst = &g_qvec[b * DD + tid * 4];
        atomicAdd(dst + 0, acc.x);
        atomicAdd(dst + 1, acc.y);
        atomicAdd(dst + 2, acc.z);
        atomicAdd(dst + 3, acc.w);
    }

    // PDL trigger (memory-clobbered: atomics stay above).
    asm volatile("griddepcontrol.launch_dependents;" ::: "memory");
}

// ---------------------------------------------------------------------------
// 2. Tail: per-batch top-5 (min-index tie-break = jax top_k) + cosine vs
//    mean question vector; global mean by ticket; resets scratch.
//    NEW: rank-based 40-candidate merge (1 pass, no extraction rounds) and
//    lane-parallel final reductions (no 10 serial warp_sums).
// grid: NB x 256 threads
// ---------------------------------------------------------------------------
__global__ void __launch_bounds__(256, 1)
tail_kernel(const float* __restrict__ ctx, float* __restrict__ out) {
    __shared__ float              s_wv[8];
    __shared__ unsigned long long s_cand[8 * TOPK];   // 40 candidates
    __shared__ int                s_top[TOPK];
    __shared__ float              s_qn;
    __shared__ float              s_red[2 * TOPK][8];

    // PDL: block until the producer grid's memory is visible.
    asm volatile("griddepcontrol.wait;" ::: "memory");

    const int b    = blockIdx.x;
    const int tid  = threadIdx.x;
    const int lane = tid & 31;
    const int wid  = tid >> 5;
    const float4 zero4 = make_float4(0.f, 0.f, 0.f, 0.f);

    // --- issue all g_avg loads first (4 independent LDG.128, L2-hot) ------
    float4 av[4];
    #pragma unroll
    for (int j = 0; j < 4; j++)
        av[j] = reinterpret_cast<const float4*>(g_avg)[b * (LC / 4) + tid + j * 256];

    // --- mean question vector + norm partial (overlaps the loads above) ---
    float4 q4 = reinterpret_cast<const float4*>(g_qvec)[b * (DD / 4) + tid];
    const float inv = 1.0f / (float)LQ;    // *2^-7: exact
    q4.x *= inv; q4.y *= inv; q4.z *= inv; q4.w *= inv;
    {
        float p = warp_sum(q4.x * q4.x + q4.y * q4.y + q4.z * q4.z + q4.w * q4.w);
        if (lane == 0) s_wv[wid] = p;
    }
    reinterpret_cast<float4*>(g_qvec)[b * (DD / 4) + tid] = zero4;

    // --- single-pass local top-5: sorted-descending key list in registers --
    unsigned long long key[TOPK] = {0ull, 0ull, 0ull, 0ull, 0ull};
    #pragma unroll
    for (int j = 0; j < 4; j++) {
        const float vv[4] = {av[j].x, av[j].y, av[j].z, av[j].w};
        #pragma unroll
        for (int c = 0; c < 4; c++) {
            int idx = (tid + j * 256) * 4 + c;
            unsigned long long k =
                ((unsigned long long)ord(vv[c]) << 32) | (unsigned)(LC - 1 - idx);
            #pragma unroll
            for (int m = 0; m < TOPK; m++) {
                unsigned long long mx = (key[m] > k) ? key[m] : k;
                k      = (key[m] > k) ? k : key[m];
                key[m] = mx;
            }
        }
        // reset scratch for next replay
        reinterpret_cast<float4*>(g_avg)[b * (LC / 4) + tid + j * 256] = zero4;
    }

    // --- per-warp top-5 via butterfly max (no block syncs) ------------------
    #pragma unroll
    for (int r = 0; r < TOPK; r++) {
        unsigned long long m = warp_max64_all(key[0]);
        if (lane == 0) s_cand[wid * TOPK + r] = m;
        if (key[0] == m) {                 // unique keys: exactly one popper
            key[0] = key[1]; key[1] = key[2];
            key[2] = key[3]; key[3] = key[4]; key[4] = 0ull;
        }
    }
    __syncthreads();                       // barrier 1: candidates + s_wv

    // --- warp0: qnorm + RANK-BASED merge of 40 candidates -------------------
    if (wid == 0) {
        float v = (lane < 8) ? s_wv[lane] : 0.0f;
        v = warp_sum(v);
        if (lane == 0) s_qn = fmaxf(sqrtf(v), EPS);

        // each lane ranks its candidate(s) among all 40 (broadcast LDS loop);
        // keys unique -> ranks unique -> the 5 winners fill s_top directly.
        unsigned long long k1 = s_cand[lane];
        unsigned long long k2 = (lane < 8) ? s_cand[32 + lane] : 0ull;
        int r1 = 0, r2 = 0;
        #pragma unroll
        for (int i = 0; i < 40; i++) {
            unsigned long long c = s_cand[i];
            r1 += (c > k1);
            r2 += (c > k2);
        }
        if (r1 < TOPK)
            s_top[r1] = LC - 1 - (int)(unsigned)(k1 & 0xffffffffu);
        if (lane < 8 && r2 < TOPK)
            s_top[r2] = LC - 1 - (int)(unsigned)(k2 & 0xffffffffu);
    }
    __syncthreads();                       // barrier 2: s_top ready

    // --- batched gather of all 5 context rows (one DRAM round-trip) ---------
    float4 cv[TOPK];
    #pragma unroll
    for (int k = 0; k < TOPK; k++)
        cv[k] = reinterpret_cast<const float4*>(ctx)
                    [((size_t)b * LC + (size_t)s_top[k]) * (DD / 4) + tid];

    // --- all 10 partial reductions, single barrier ---------------------------
    #pragma unroll
    for (int k = 0; k < TOPK; k++) {
        float d = warp_sum(cv[k].x * q4.x + cv[k].y * q4.y +
                           cv[k].z * q4.z + cv[k].w * q4.w);
        float n = warp_sum(cv[k].x * cv[k].x + cv[k].y * cv[k].y +
                           cv[k].z * cv[k].z + cv[k].w * cv[k].w);
        if (lane == 0) { s_red[k][wid] = d; s_red[TOPK + k][wid] = n; }
    }
    __syncthreads();                       // barrier 3: partials ready

    // --- lane-parallel final reduce: lane j<10 totals its row of 8 ----------
    if (wid == 0) {
        float tot = 0.0f;
        if (lane < 2 * TOPK) {
            #pragma unroll
            for (int i = 0; i < 8; i++) tot += s_red[lane][i];
        }
        // lane j<5: dd = tot_j, nn = tot_{5+j}
        float nn = __shfl_down_sync(0xffffffffu, tot, TOPK);
        float c = 0.0f;
        if (lane < TOPK)
            c = 1.0f - tot / (s_qn * fmaxf(sqrtf(nn), EPS));
        // collapse the 5 contributions (lanes 5..7 hold c = 0)
        c += __shfl_down_sync(0xffffffffu, c, 4);
        c += __shfl_down_sync(0xffffffffu, c, 2);
        c += __shfl_down_sync(0xffffffffu, c, 1);

        if (lane == 0) {
            atomicAdd(&g_loss_sum, c);
            __threadfence();
            int t = atomicAdd(&g_done, 1);
            if (t == NB - 1) {
                __threadfence();
                float total = atomicAdd(&g_loss_sum, 0.0f);  // coherent read
                out[0] = total / (float)(NB * TOPK);
                g_loss_sum = 0.0f;             // reset for next replay
                g_done     = 0;
            }
        }
    }
}

// ---------------------------------------------------------------------------
extern "C" void kernel_launch(void* const* d_in, const int* in_sizes, int n_in,
                              void* d_out, int out_size) {
    const float* q   = (const float*)d_in[0];  // question_emb  [8,128,1024]
    const float* ctx = (const float*)d_in[1];  // context_emb   [8,4096,1024]
    const float* w   = (const float*)d_in[2];  // cross_attn    [8,16,128,4096]

    fused_reduce<<<1024 + 64, 256>>>((const float4*)w, (const float4*)q);

    // Tail with programmatic dependent launch (R14-proven: nets ~0.3 us).
    cudaLaunchAttribute attrs[1];
    attrs[0].id = cudaLaunchAttributeProgrammaticStreamSerialization;
    attrs[0].val.programmaticStreamSerializationAllowed = 1;

    cudaLaunchConfig_t cfg = {};
    cfg.gridDim  = dim3(NB, 1, 1);
    cfg.blockDim = dim3(256, 1, 1);
    cfg.dynamicSmemBytes = 0;
    cfg.stream   = 0;
    cfg.attrs    = attrs;
    cfg.numAttrs = 1;

    cudaLaunchKernelEx(&cfg, tail_kernel, ctx, (float*)d_out);
}

// round 17
// speedup vs baseline: 1.0426x; 1.0013x over previous
#include <cuda_runtime.h>
#include <math.h>

#define NB   8
#define NH   16
#define LQ   128
#define LC   4096
#define DD   1024
#define HL   (NH * LQ)   // 2048
#define TOPK 5
#define EPS  1e-8f

// Scratch (__device__ globals; zero-initialized at load; tail resets what it
// reads, so graph replays are self-consistent with no zero kernel).
__device__ float g_avg[NB * LC];
__device__ float g_qvec[NB * DD];
__device__ float g_loss_sum;
__device__ int   g_done;

// ---------------------------------------------------------------------------
// helpers
// ---------------------------------------------------------------------------
__device__ __forceinline__ float warp_sum(float v) {
    #pragma unroll
    for (int off = 16; off > 0; off >>= 1)
        v += __shfl_down_sync(0xffffffffu, v, off);
    return v;
}
// butterfly max: every lane ends with the warp max
__device__ __forceinline__ unsigned long long warp_max64_all(unsigned long long k) {
    #pragma unroll
    for (int off = 16; off > 0; off >>= 1) {
        unsigned long long o = __shfl_xor_sync(0xffffffffu, k, off);
        if (o > k) k = o;
    }
    return k;
}
// orderable mapping: preserves float total order as unsigned compare
__device__ __forceinline__ unsigned ord(float f) {
    unsigned fb = __float_as_uint(f);
    unsigned m  = (unsigned)((int)fb >> 31);
    return fb ^ (m | 0x80000000u);
}

// ---------------------------------------------------------------------------
// 1. Stream (R14-proven, byte-identical: scheme A + __ldcs, ~6.4 TB/s):
//    1024 attn blocks (64-row sequential chunks, 32-way atomic merge)
//    + 64 qvec blocks. PDL trigger after the atomics.
// ---------------------------------------------------------------------------
__global__ void __launch_bounds__(256)
fused_reduce(const float4* __restrict__ w, const float4* __restrict__ q) {
    const int id = blockIdx.x;

    if (id < 1024) {                       // ---- attn part (256 MB read) ----
        const int b      = id >> 7;
        const int rem    = id & 127;
        const int seg    = rem >> 2;       // 0..31
        const int cchunk = rem & 3;        // 0..3
        const int lc4    = cchunk * 256 + threadIdx.x;
        const int ROWS   = HL / 32;        // 64

        float4 acc = make_float4(0.f, 0.f, 0.f, 0.f);
        const float4* p = w + ((size_t)b * HL + (size_t)seg * ROWS) * (LC / 4) + lc4;

        #pragma unroll 16
        for (int r = 0; r < ROWS; r++) {
            float4 v = __ldcs(p + (size_t)r * (LC / 4));   // evict-first
            acc.x += v.x; acc.y += v.y; acc.z += v.z; acc.w += v.w;
        }
        float* dst = &g_avg[b * LC + lc4 * 4];
        atomicAdd(dst + 0, acc.x);
        atomicAdd(dst + 1, acc.y);
        atomicAdd(dst + 2, acc.z);
        atomicAdd(dst + 3, acc.w);
    } else {                               // ---- question part (4 MB) ----
        const int id2 = id - 1024;
        const int b   = id2 >> 3;
        const int seg = id2 & 7;           // 16 lq rows each
        const int tid = threadIdx.x;

        float4 acc = make_float4(0.f, 0.f, 0.f, 0.f);
        const float4* p = q + ((size_t)b * LQ + (size_t)seg * 16) * (DD / 4) + tid;

        #pragma unroll
        for (int r = 0; r < 16; r++) {
            float4 v = __ldcs(p + (size_t)r * (DD / 4));   // evict-first
            acc.x += v.x; acc.y += v.y; acc.z += v.z; acc.w += v.w;
        }
        float* dst = &g_qvec[b * DD + tid * 4];
        atomicAdd(dst + 0, acc.x);
        atomicAdd(dst + 1, acc.y);
        atomicAdd(dst + 2, acc.z);
        atomicAdd(dst + 3, acc.w);
    }

    // PDL trigger (memory-clobbered: atomics stay above).
    asm volatile("griddepcontrol.launch_dependents;" ::: "memory");
}

// ---------------------------------------------------------------------------
// 2. Tail: per-batch top-5 (min-index tie-break = jax top_k) + cosine vs
//    mean question vector; global mean by ticket; resets scratch.
//    NEW: rank-based 40-candidate merge (1 pass, no extraction rounds) and
//    lane-parallel final reductions (no 10 serial warp_sums).
// grid: NB x 256 threads
// ---------------------------------------------------------------------------
__global__ void __launch_bounds__(256, 1)
tail_kernel(const float* __restrict__ ctx, float* __restrict__ out) {
    __shared__ float              s_wv[8];
    __shared__ unsigned long long s_cand[8 * TOPK];   // 40 candidates
    __shared__ int                s_top[TOPK];
    __shared__ float              s_qn;
    __shared__ float              s_red[2 * TOPK][8];

    // PDL: block until the producer grid's memory is visible.
    asm volatile("griddepcontrol.wait;" ::: "memory");

    const int b    = blockIdx.x;
    const int tid  = threadIdx.x;
    const int lane = tid & 31;
    const int wid  = tid >> 5;
    const float4 zero4 = make_float4(0.f, 0.f, 0.f, 0.f);

    // --- issue all g_avg loads first (4 independent LDG.128, L2-hot) ------
    float4 av[4];
    #pragma unroll
    for (int j = 0; j < 4; j++)
        av[j] = reinterpret_cast<const float4*>(g_avg)[b * (LC / 4) + tid + j * 256];

    // --- mean question vector + norm partial (overlaps the loads above) ---
    float4 q4 = reinterpret_cast<const float4*>(g_qvec)[b * (DD / 4) + tid];
    const float inv = 1.0f / (float)LQ;    // *2^-7: exact
    q4.x *= inv; q4.y *= inv; q4.z *= inv; q4.w *= inv;
    {
        float p = warp_sum(q4.x * q4.x + q4.y * q4.y + q4.z * q4.z + q4.w * q4.w);
        if (lane == 0) s_wv[wid] = p;
    }
    reinterpret_cast<float4*>(g_qvec)[b * (DD / 4) + tid] = zero4;

    // --- single-pass local top-5: sorted-descending key list in registers --
    unsigned long long key[TOPK] = {0ull, 0ull, 0ull, 0ull, 0ull};
    #pragma unroll
    for (int j = 0; j < 4; j++) {
        const float vv[4] = {av[j].x, av[j].y, av[j].z, av[j].w};
        #pragma unroll
        for (int c = 0; c < 4; c++) {
            int idx = (tid + j * 256) * 4 + c;
            unsigned long long k =
                ((unsigned long long)ord(vv[c]) << 32) | (unsigned)(LC - 1 - idx);
            #pragma unroll
            for (int m = 0; m < TOPK; m++) {
                unsigned long long mx = (key[m] > k) ? key[m] : k;
                k      = (key[m] > k) ? k : key[m];
                key[m] = mx;
            }
        }
        // reset scratch for next replay
        reinterpret_cast<float4*>(g_avg)[b * (LC / 4) + tid + j * 256] = zero4;
    }

    // --- per-warp top-5 via butterfly max (no block syncs) ------------------
    #pragma unroll
    for (int r = 0; r < TOPK; r++) {
        unsigned long long m = warp_max64_all(key[0]);
        if (lane == 0) s_cand[wid * TOPK + r] = m;
        if (key[0] == m) {                 // unique keys: exactly one popper
            key[0] = key[1]; key[1] = key[2];
            key[2] = key[3]; key[3] = key[4]; key[4] = 0ull;
        }
    }
    __syncthreads();                       // barrier 1: candidates + s_wv

    // --- warp0: qnorm + RANK-BASED merge of 40 candidates -------------------
    if (wid == 0) {
        float v = (lane < 8) ? s_wv[lane] : 0.0f;
        v = warp_sum(v);
        if (lane == 0) s_qn = fmaxf(sqrtf(v), EPS);

        // each lane ranks its candidate(s) among all 40 (broadcast LDS loop);
        // keys unique -> ranks unique -> the 5 winners fill s_top directly.
        unsigned long long k1 = s_cand[lane];
        unsigned long long k2 = (lane < 8) ? s_cand[32 + lane] : 0ull;
        int r1 = 0, r2 = 0;
        #pragma unroll
        for (int i = 0; i < 40; i++) {
            unsigned long long c = s_cand[i];
            r1 += (c > k1);
            r2 += (c > k2);
        }
        if (r1 < TOPK)
            s_top[r1] = LC - 1 - (int)(unsigned)(k1 & 0xffffffffu);
        if (lane < 8 && r2 < TOPK)
            s_top[r2] = LC - 1 - (int)(unsigned)(k2 & 0xffffffffu);
    }
    __syncthreads();                       // barrier 2: s_top ready

    // --- batched gather of all 5 context rows (one DRAM round-trip) ---------
    float4 cv[TOPK];
    #pragma unroll
    for (int k = 0; k < TOPK; k++)
        cv[k] = reinterpret_cast<const float4*>(ctx)
                    [((size_t)b * LC + (size_t)s_top[k]) * (DD / 4) + tid];

    // --- all 10 partial reductions, single barrier ---------------------------
    #pragma unroll
    for (int k = 0; k < TOPK; k++) {
        float d = warp_sum(cv[k].x * q4.x + cv[k].y * q4.y +
                           cv[k].z * q4.z + cv[k].w * q4.w);
        float n = warp_sum(cv[k].x * cv[k].x + cv[k].y * cv[k].y +
                           cv[k].z * cv[k].z + cv[k].w * cv[k].w);
        if (lane == 0) { s_red[k][wid] = d; s_red[TOPK + k][wid] = n; }
    }
    __syncthreads();                       // barrier 3: partials ready

    // --- lane-parallel final reduce: lane j<10 totals its row of 8 ----------
    if (wid == 0) {
        float tot = 0.0f;
        if (lane < 2 * TOPK) {
            #pragma unroll
            for (int i = 0; i < 8; i++) tot += s_red[lane][i];
        }
        // lane j<5: dd = tot_j, nn = tot_{5+j}
        float nn = __shfl_down_sync(0xffffffffu, tot, TOPK);
        float c = 0.0f;
        if (lane < TOPK)
            c = 1.0f - tot / (s_qn * fmaxf(sqrtf(nn), EPS));
        // collapse the 5 contributions (lanes 5..7 hold c = 0)
        c += __shfl_down_sync(0xffffffffu, c, 4);
        c += __shfl_down_sync(0xffffffffu, c, 2);
        c += __shfl_down_sync(0xffffffffu, c, 1);

        if (lane == 0) {
            atomicAdd(&g_loss_sum, c);
            __threadfence();
            int t = atomicAdd(&g_done, 1);
            if (t == NB - 1) {
                __threadfence();
                float total = atomicAdd(&g_loss_sum, 0.0f);  // coherent read
                out[0] = total / (float)(NB * TOPK);
                g_loss_sum = 0.0f;             // reset for next replay
                g_done     = 0;
            }
        }
    }
}

// ---------------------------------------------------------------------------
extern "C" void kernel_launch(void* const* d_in, const int* in_sizes, int n_in,
                              void* d_out, int out_size) {
    const float* q   = (const float*)d_in[0];  // question_emb  [8,128,1024]
    const float* ctx = (const float*)d_in[1];  // context_emb   [8,4096,1024]
    const float* w   = (const float*)d_in[2];  // cross_attn    [8,16,128,4096]

    fused_reduce<<<1024 + 64, 256>>>((const float4*)w, (const float4*)q);

    // Tail with programmatic dependent launch (R14-proven: nets ~0.3 us).
    cudaLaunchAttribute attrs[1];
    attrs[0].id = cudaLaunchAttributeProgrammaticStreamSerialization;
    attrs[0].val.programmaticStreamSerializationAllowed = 1;

    cudaLaunchConfig_t cfg = {};
    cfg.gridDim  = dim3(NB, 1, 1);
    cfg.blockDim = dim3(256, 1, 1);
    cfg.dynamicSmemBytes = 0;
    cfg.stream   = 0;
    cfg.attrs    = attrs;
    cfg.numAttrs = 1;

    cudaLaunchKernelEx(&cfg, tail_kernel, ctx, (float*)d_out);
}